// round 13
// baseline (speedup 1.0000x reference)
#include <cuda_runtime.h>
#include <stdint.h>

#define BATCH   2
#define SEQ     2048
#define DIM     1024
#define NHEAD   16
#define HDIM    64
#define MAXLEN  2048
#define BN      (BATCH*SEQ)

// ---------------- scratch (device globals; allocation is forbidden) ----------------
__device__ float g_Q[(size_t)BATCH * NHEAD * SEQ * HDIM];   // [(b*H+h)][n][hd]
__device__ float g_K[(size_t)BATCH * NHEAD * SEQ * HDIM];
__device__ float g_V[(size_t)BATCH * NHEAD * SEQ * HDIM];
__device__ float g_O[(size_t)BATCH * SEQ * DIM];            // [b][n][h*HD+hd], tf32-rounded
__device__ float g_xc [(size_t)BN * DIM];                   // tf32-rounded copies
__device__ float g_Wqc[(size_t)DIM * DIM];
__device__ float g_Wkc[(size_t)DIM * DIM];
__device__ float g_Wvc[(size_t)DIM * DIM];
__device__ float g_Wpc[(size_t)DIM * DIM];

// ---------------- helpers ----------------
__device__ __forceinline__ uint32_t f2t(float f) {
    uint32_t u;
    asm("cvt.rna.tf32.f32 %0, %1;" : "=r"(u) : "f"(f));
    return u;
}
__device__ __forceinline__ float f2tf(float f) {
    return __uint_as_float(f2t(f));
}
__device__ __forceinline__ void mma8(float c[4],
                                     uint32_t a0, uint32_t a1, uint32_t a2, uint32_t a3,
                                     uint32_t b0, uint32_t b1) {
    asm volatile(
        "mma.sync.aligned.m16n8k8.row.col.f32.tf32.tf32.f32 "
        "{%0,%1,%2,%3},{%4,%5,%6,%7},{%8,%9},{%0,%1,%2,%3};"
        : "+f"(c[0]), "+f"(c[1]), "+f"(c[2]), "+f"(c[3])
        : "r"(a0), "r"(a1), "r"(a2), "r"(a3), "r"(b0), "r"(b1));
}
#define U(x) __float_as_uint(x)

__device__ __forceinline__ void cp16(uint32_t saddr, const float* gptr) {
    asm volatile("cp.async.cg.shared.global [%0], [%1], 16;" :: "r"(saddr), "l"(gptr));
}
#define CP_COMMIT() asm volatile("cp.async.commit_group;")

// chunk swizzle for 64-word permuted rows (attention)
__device__ __forceinline__ int swz(int row) {
    return ((row & 1) << 2) | ((row >> 1) & 3);
}
__device__ __forceinline__ void stash_perm(float* rowp, int c4, float4 v, int s) {
    int a4 = 4 * (c4 >> 4);
    int wd = (c4 & 15) >> 2;
    rowp[4 * ((a4 + 0) ^ s) + wd] = v.x;
    rowp[4 * ((a4 + 1) ^ s) + wd] = v.y;
    rowp[4 * ((a4 + 2) ^ s) + wd] = v.z;
    rowp[4 * ((a4 + 3) ^ s) + wd] = v.w;
}
__device__ __forceinline__ float4 frag4(const float* S, int stride, int row, int kb, int t) {
    return *(const float4*)&S[row * stride + 4 * ((4 * kb + t) ^ swz(row))];
}

// ---------------- prologue: RNA-round fp32 -> tf32 bits (once) ----------------
__global__ void cvt_tf32_k(const float4* __restrict__ s, int which, int n4) {
    int i = blockIdx.x * 256 + threadIdx.x;
    if (i >= n4) return;
    float* dsts[5] = {g_xc, g_Wqc, g_Wkc, g_Wvc, g_Wpc};
    float4 v = s[i];
    ((float4*)dsts[which])[i] =
        make_float4(f2tf(v.x), f2tf(v.y), f2tf(v.z), f2tf(v.w));
}

// ---------------- GEMMs: cp.async staged, pad-20 rows, double-buffered ----------------
#define GP 20
#define KBLK 16
#define NKB (DIM / KBLK)

// fused QKV: C_sel[m,n] = sum_k xc[m,k] * W_sel[n,k]; scatter to g_Q/g_K/g_V
__global__ __launch_bounds__(256, 1)
void gemm_qkv()
{
    extern __shared__ float dsm[];
    float* As = dsm;                    // [2][128*GP]
    float* Bs = dsm + 2 * 128 * GP;     // [2][3][128*GP]

    const int m0 = blockIdx.y * 128;
    const int n0 = blockIdx.x * 128;
    const int tid = threadIdx.x;
    const int w = tid >> 5, lane = tid & 31, g = lane >> 2, t = lane & 3;
    const int wy = w >> 2, wx = w & 3;   // 2x4 warp grid; warp tile 64x32

    const int srow = tid >> 2;           // 0..63
    const int sc4  = (tid & 3) << 2;     // 0,4,8,12

    const float* Wsel[3] = {g_Wqc, g_Wkc, g_Wvc};
    float* Dsel[3] = {g_Q, g_K, g_V};

    float acc[3][4][4][4];
#pragma unroll
    for (int s = 0; s < 3; s++)
#pragma unroll
        for (int i = 0; i < 4; i++)
#pragma unroll
            for (int j = 0; j < 4; j++)
#pragma unroll
                for (int e = 0; e < 4; e++) acc[s][i][j][e] = 0.f;

    const uint32_t sA = (uint32_t)__cvta_generic_to_shared(As);
    const uint32_t sB = (uint32_t)__cvta_generic_to_shared(Bs);

    auto issue_tile = [&](int buf, int k0) {
        uint32_t a0 = sA + (uint32_t)(buf * 128 * GP + srow * GP + sc4) * 4;
        cp16(a0,                g_xc + (size_t)(m0 + srow)      * DIM + k0 + sc4);
        cp16(a0 + 64 * GP * 4,  g_xc + (size_t)(m0 + srow + 64) * DIM + k0 + sc4);
#pragma unroll
        for (int s = 0; s < 3; s++) {
            uint32_t b0 = sB + (uint32_t)((buf * 3 + s) * 128 * GP + srow * GP + sc4) * 4;
            cp16(b0,               Wsel[s] + (size_t)(n0 + srow)      * DIM + k0 + sc4);
            cp16(b0 + 64 * GP * 4, Wsel[s] + (size_t)(n0 + srow + 64) * DIM + k0 + sc4);
        }
    };

    issue_tile(0, 0);
    CP_COMMIT();

    for (int kb = 0; kb < NKB; kb++) {
        const int cur = kb & 1;
        if (kb + 1 < NKB) {
            issue_tile(cur ^ 1, (kb + 1) * KBLK);
            CP_COMMIT();
            asm volatile("cp.async.wait_group 1;");
        } else {
            asm volatile("cp.async.wait_group 0;");
        }
        __syncthreads();

        const float* A = As + cur * 128 * GP;
        float aA[4][2][4];
#pragma unroll
        for (int mt = 0; mt < 4; mt++) {
            int r = wy * 64 + mt * 16 + g;
#pragma unroll
            for (int j = 0; j < 4; j++) {
                aA[mt][0][j] = A[r * GP + t + 4 * j];
                aA[mt][1][j] = A[(r + 8) * GP + t + 4 * j];
            }
        }
#pragma unroll
        for (int s = 0; s < 3; s++) {
            const float* B = Bs + (cur * 3 + s) * 128 * GP;
            float bf[4][4];
#pragma unroll
            for (int nt = 0; nt < 4; nt++) {
                int c = wx * 32 + nt * 8 + g;
#pragma unroll
                for (int j = 0; j < 4; j++) bf[nt][j] = B[c * GP + t + 4 * j];
            }
#pragma unroll
            for (int mt = 0; mt < 4; mt++)
#pragma unroll
                for (int nt = 0; nt < 4; nt++) {
                    mma8(acc[s][mt][nt],
                         U(aA[mt][0][0]), U(aA[mt][1][0]), U(aA[mt][0][1]), U(aA[mt][1][1]),
                         U(bf[nt][0]), U(bf[nt][1]));
                    mma8(acc[s][mt][nt],
                         U(aA[mt][0][2]), U(aA[mt][1][2]), U(aA[mt][0][3]), U(aA[mt][1][3]),
                         U(bf[nt][2]), U(bf[nt][3]));
                }
        }
        __syncthreads();
    }

#pragma unroll
    for (int s = 0; s < 3; s++) {
        float* dst = Dsel[s];
#pragma unroll
        for (int mt = 0; mt < 4; mt++) {
            int rbase = wy * 64 + mt * 16 + g;
#pragma unroll
            for (int nt = 0; nt < 4; nt++) {
                int cbase = wx * 32 + nt * 8 + 2 * t;
#pragma unroll
                for (int e = 0; e < 4; e++) {
                    int gm = m0 + rbase + ((e >= 2) ? 8 : 0);
                    int gn = n0 + cbase + (e & 1);
                    int bb = gm / SEQ, nrow = gm % SEQ;
                    int hh = gn / HDIM, hd = gn % HDIM;
                    dst[(((size_t)bb * NHEAD + hh) * SEQ + nrow) * HDIM + hd] =
                        acc[s][mt][nt][e];
                }
            }
        }
    }
}

// output GEMM: out[m,n] = sum_k g_O[m,k] * Wpc[n,k] + bias[n]
__global__ __launch_bounds__(256, 2)
void gemm_out(const float* __restrict__ bias, float* __restrict__ Cext)
{
    __shared__ float As[2][128 * GP];
    __shared__ float Bs[2][128 * GP];

    const int m0 = blockIdx.y * 128;
    const int n0 = blockIdx.x * 128;
    const int tid = threadIdx.x;
    const int w = tid >> 5, lane = tid & 31, g = lane >> 2, t = lane & 3;
    const int wy = w >> 2, wx = w & 3;

    const int srow = tid >> 2;
    const int sc4  = (tid & 3) << 2;

    float acc[4][4][4];
#pragma unroll
    for (int i = 0; i < 4; i++)
#pragma unroll
        for (int j = 0; j < 4; j++)
#pragma unroll
            for (int e = 0; e < 4; e++) acc[i][j][e] = 0.f;

    const uint32_t sA = (uint32_t)__cvta_generic_to_shared(&As[0][0]);
    const uint32_t sB = (uint32_t)__cvta_generic_to_shared(&Bs[0][0]);

    auto issue_tile = [&](int buf, int k0) {
        uint32_t a0 = sA + (uint32_t)(buf * 128 * GP + srow * GP + sc4) * 4;
        cp16(a0,               g_O + (size_t)(m0 + srow)      * DIM + k0 + sc4);
        cp16(a0 + 64 * GP * 4, g_O + (size_t)(m0 + srow + 64) * DIM + k0 + sc4);
        uint32_t b0 = sB + (uint32_t)(buf * 128 * GP + srow * GP + sc4) * 4;
        cp16(b0,               g_Wpc + (size_t)(n0 + srow)      * DIM + k0 + sc4);
        cp16(b0 + 64 * GP * 4, g_Wpc + (size_t)(n0 + srow + 64) * DIM + k0 + sc4);
    };

    issue_tile(0, 0);
    CP_COMMIT();

    for (int kb = 0; kb < NKB; kb++) {
        const int cur = kb & 1;
        if (kb + 1 < NKB) {
            issue_tile(cur ^ 1, (kb + 1) * KBLK);
            CP_COMMIT();
            asm volatile("cp.async.wait_group 1;");
        } else {
            asm volatile("cp.async.wait_group 0;");
        }
        __syncthreads();

        const float* A = &As[cur][0];
        const float* B = &Bs[cur][0];
        float aA[4][2][4], bf[4][4];
#pragma unroll
        for (int mt = 0; mt < 4; mt++) {
            int r = wy * 64 + mt * 16 + g;
#pragma unroll
            for (int j = 0; j < 4; j++) {
                aA[mt][0][j] = A[r * GP + t + 4 * j];
                aA[mt][1][j] = A[(r + 8) * GP + t + 4 * j];
            }
        }
#pragma unroll
        for (int nt = 0; nt < 4; nt++) {
            int c = wx * 32 + nt * 8 + g;
#pragma unroll
            for (int j = 0; j < 4; j++) bf[nt][j] = B[c * GP + t + 4 * j];
        }
#pragma unroll
        for (int mt = 0; mt < 4; mt++)
#pragma unroll
            for (int nt = 0; nt < 4; nt++) {
                mma8(acc[mt][nt],
                     U(aA[mt][0][0]), U(aA[mt][1][0]), U(aA[mt][0][1]), U(aA[mt][1][1]),
                     U(bf[nt][0]), U(bf[nt][1]));
                mma8(acc[mt][nt],
                     U(aA[mt][0][2]), U(aA[mt][1][2]), U(aA[mt][0][3]), U(aA[mt][1][3]),
                     U(bf[nt][2]), U(bf[nt][3]));
            }
        __syncthreads();
    }

#pragma unroll
    for (int mt = 0; mt < 4; mt++) {
        int rbase = wy * 64 + mt * 16 + g;
#pragma unroll
        for (int nt = 0; nt < 4; nt++) {
            int cbase = wx * 32 + nt * 8 + 2 * t;
#pragma unroll
            for (int e = 0; e < 4; e++) {
                int gm = m0 + rbase + ((e >= 2) ? 8 : 0);
                int gn = n0 + cbase + (e & 1);
                Cext[(size_t)gm * DIM + gn] = acc[mt][nt][e] + bias[gn];
            }
        }
    }
}

// ---------------- fused causal attention with skewed relative positions ----------------
// srel[r,c] = q_{r-1} . e_{N-(r-c)} for c<r, 0 at c==r (via zero-filled E rows >= N).
// sQ/sK/sE: permuted 64-word rows. sVT: V TRANSPOSED [hd][token], permuted -> PV uses LDS.128.
// sE ring: 64 new rows staged per k-tile. P permuted into dead sQ region.
#define GBW 65
#define ATTN_SMEM_FLOATS (65*64 + 64*64 + 64*64 + 128*64 + 64*GBW)
#define ATTN_SMEM_BYTES  (ATTN_SMEM_FLOATS * 4)

__global__ __launch_bounds__(128, 2)
void attn_kernel(const float* __restrict__ rel)
{
    extern __shared__ float sm[];
    float* sQ  = sm;                    // [65][64] perm tf32; reused as P
    float* sK  = sQ + 65 * 64;          // [64][64] perm raw fp32
    float* sVT = sK + 64 * 64;          // [64][64] perm tf32, V^T (row=hd, col=token)
    float* sE  = sVT + 64 * 64;         // [128][64] perm raw fp32, ring
    float* sGb = sE + 128 * 64;         // [64][GBW] G band (scalar)
    float* sP  = sQ;

    const int qt = (gridDim.x - 1) - blockIdx.x;   // 31..0 (long CTAs first)
    const int bh = blockIdx.y;
    const int r0 = qt * 64;
    const int b  = bh / NHEAD;
    const int h  = bh % NHEAD;
    const int hcol = h * HDIM;

    const float* Qg = g_Q + (size_t)bh * SEQ * HDIM;
    const float* Kg = g_K + (size_t)bh * SEQ * HDIM;
    const float* Vg = g_V + (size_t)bh * SEQ * HDIM;

    const int tid = threadIdx.x;
    const int w = tid >> 5, lane = tid & 31, g = lane >> 2, t = lane & 3;
    const int rA = w * 16 + g;

    for (int idx = tid; idx < 65 * 16; idx += 128) {
        int row = idx >> 4, c4 = (idx & 15) << 2;
        int gr = r0 - 1 + row; if (gr < 0) gr = 0;
        float4 v = *(const float4*)(Qg + (size_t)gr * HDIM + c4);
        stash_perm(sQ + row * 64, c4,
                   make_float4(f2tf(v.x), f2tf(v.y), f2tf(v.z), f2tf(v.w)),
                   swz(row));
    }
    __syncthreads();

    uint32_t aQ[8][4], aQp[8][4];
#pragma unroll
    for (int kb = 0; kb < 4; kb++) {
        float4 f;
        f = frag4(sQ, 64, 1 + rA, kb, t);
        aQ[2*kb][0] = U(f.x); aQ[2*kb][2] = U(f.y);
        aQ[2*kb+1][0] = U(f.z); aQ[2*kb+1][2] = U(f.w);
        f = frag4(sQ, 64, 9 + rA, kb, t);
        aQ[2*kb][1] = U(f.x); aQ[2*kb][3] = U(f.y);
        aQ[2*kb+1][1] = U(f.z); aQ[2*kb+1][3] = U(f.w);
        f = frag4(sQ, 64, rA, kb, t);
        aQp[2*kb][0] = U(f.x); aQp[2*kb][2] = U(f.y);
        aQp[2*kb+1][0] = U(f.z); aQp[2*kb+1][2] = U(f.w);
        f = frag4(sQ, 64, 8 + rA, kb, t);
        aQp[2*kb][1] = U(f.x); aQp[2*kb][3] = U(f.y);
        aQp[2*kb+1][1] = U(f.z); aQp[2*kb+1][3] = U(f.w);
    }

    float Oacc[8][4];
#pragma unroll
    for (int i = 0; i < 8; i++)
#pragma unroll
        for (int e = 0; e < 4; e++) Oacc[i][e] = 0.f;
    float m0r = -1e30f, m1r = -1e30f;
    float l0r = 0.f,    l1r = 0.f;

    for (int j = 0; j <= qt; j++) {
        const int c0 = j * 64;
        const int ph = (j & 1) << 6;
        __syncthreads();

        // K: perm raw fp32 (coalesced LDG)
        for (int idx = tid; idx < 64 * 16; idx += 128) {
            int row = idx >> 4, c4 = (idx & 15) << 2;
            float4 kv = *(const float4*)(Kg + (size_t)(c0 + row) * HDIM + c4);
            stash_perm(sK + row * 64, c4, kv, swz(row));
        }
        // V transposed: lanes stride tokens (conflict-free scatter STS)
        for (int idx = tid; idx < 64 * 16; idx += 128) {
            int tok = idx & 63, c4 = (idx >> 6) << 2;
            float4 vv = *(const float4*)(Vg + (size_t)(c0 + tok) * HDIM + c4);
            float vals[4] = {f2tf(vv.x), f2tf(vv.y), f2tf(vv.z), f2tf(vv.w)};
            int chn = 4 * (tok >> 4) + (tok & 3);
            int wd  = (tok & 15) >> 2;
#pragma unroll
            for (int i = 0; i < 4; i++) {
                int r = c4 + i;
                sVT[r * 64 + 4 * (chn ^ swz(r)) + wd] = vals[i];
            }
        }
        // E ring: perm raw fp32
        const int elog0 = SEQ - r0 + c0 - 63;
        const int rbase = (j == 0) ? 0 : 64;
        for (int idx = tid; idx < (128 - rbase) * 16; idx += 128) {
            int row = rbase + (idx >> 4), c4 = (idx & 15) << 2;
            int el = elog0 + row;
            float4 ev = make_float4(0.f, 0.f, 0.f, 0.f);
            if (el < SEQ)
                ev = *(const float4*)(rel + (size_t)(el + (MAXLEN - SEQ)) * DIM + hcol + c4);
            int pr = row ^ ph;
            stash_perm(sE + pr * 64, c4, ev, swz(pr));
        }
        __syncthreads();

        // G band = Qprev @ Ewin^T (warp-trimmed)
        const int nt0 = 6 - 2 * w;
#pragma unroll
        for (int ntl = 0; ntl < 10; ntl++) {
            const int nt = nt0 + ntl;
            float ga[4] = {0.f, 0.f, 0.f, 0.f};
            const int pr = (nt * 8 + g) ^ ph;
            float4 f0 = frag4(sE, 64, pr, 0, t);
            float4 f1 = frag4(sE, 64, pr, 1, t);
            float4 f2 = frag4(sE, 64, pr, 2, t);
            float4 f3 = frag4(sE, 64, pr, 3, t);
            mma8(ga, aQp[0][0], aQp[0][1], aQp[0][2], aQp[0][3], U(f0.x), U(f0.y));
            mma8(ga, aQp[1][0], aQp[1][1], aQp[1][2], aQp[1][3], U(f0.z), U(f0.w));
            mma8(ga, aQp[2][0], aQp[2][1], aQp[2][2], aQp[2][3], U(f1.x), U(f1.y));
            mma8(ga, aQp[3][0], aQp[3][1], aQp[3][2], aQp[3][3], U(f1.z), U(f1.w));
            mma8(ga, aQp[4][0], aQp[4][1], aQp[4][2], aQp[4][3], U(f2.x), U(f2.y));
            mma8(ga, aQp[5][0], aQp[5][1], aQp[5][2], aQp[5][3], U(f2.z), U(f2.w));
            mma8(ga, aQp[6][0], aQp[6][1], aQp[6][2], aQp[6][3], U(f3.x), U(f3.y));
            mma8(ga, aQp[7][0], aQp[7][1], aQp[7][2], aQp[7][3], U(f3.z), U(f3.w));
            const int cc = nt * 8 + 2 * t;
            const int i0 = cc + rA - 63;
            const int i2 = i0 + 8;
            if (i0 >= 0     && i0 < 64)     sGb[(rA)     * GBW + i0]     = ga[0];
            if (i0 + 1 >= 0 && i0 + 1 < 64) sGb[(rA)     * GBW + i0 + 1] = ga[1];
            if (i2 >= 0     && i2 < 64)     sGb[(rA + 8) * GBW + i2]     = ga[2];
            if (i2 + 1 >= 0 && i2 + 1 < 64) sGb[(rA + 8) * GBW + i2 + 1] = ga[3];
        }
        __syncwarp();

        // S = Q @ K^T + srel (band gather), mask, scale
        float Sreg[8][4];
        float tmax0 = -1e30f, tmax1 = -1e30f;
#pragma unroll
        for (int nt = 0; nt < 8; nt++) {
            float* s = Sreg[nt];
            s[0] = s[1] = s[2] = s[3] = 0.f;
            const int kr = nt * 8 + g;
            float4 f0 = frag4(sK, 64, kr, 0, t);
            float4 f1 = frag4(sK, 64, kr, 1, t);
            float4 f2 = frag4(sK, 64, kr, 2, t);
            float4 f3 = frag4(sK, 64, kr, 3, t);
            mma8(s, aQ[0][0], aQ[0][1], aQ[0][2], aQ[0][3], U(f0.x), U(f0.y));
            mma8(s, aQ[1][0], aQ[1][1], aQ[1][2], aQ[1][3], U(f0.z), U(f0.w));
            mma8(s, aQ[2][0], aQ[2][1], aQ[2][2], aQ[2][3], U(f1.x), U(f1.y));
            mma8(s, aQ[3][0], aQ[3][1], aQ[3][2], aQ[3][3], U(f1.z), U(f1.w));
            mma8(s, aQ[4][0], aQ[4][1], aQ[4][2], aQ[4][3], U(f2.x), U(f2.y));
            mma8(s, aQ[5][0], aQ[5][1], aQ[5][2], aQ[5][3], U(f2.z), U(f2.w));
            mma8(s, aQ[6][0], aQ[6][1], aQ[6][2], aQ[6][3], U(f3.x), U(f3.y));
            mma8(s, aQ[7][0], aQ[7][1], aQ[7][2], aQ[7][3], U(f3.z), U(f3.w));

            const int cc0 = nt * 8 + 2 * t;
            float v;
            v = (s[0] + sGb[rA * GBW + cc0]) * 0.125f;
            if (c0 + cc0 > r0 + rA) v = -1e30f;
            s[0] = v; tmax0 = fmaxf(tmax0, v);

            v = (s[1] + sGb[rA * GBW + cc0 + 1]) * 0.125f;
            if (c0 + cc0 + 1 > r0 + rA) v = -1e30f;
            s[1] = v; tmax0 = fmaxf(tmax0, v);

            v = (s[2] + sGb[(rA + 8) * GBW + cc0]) * 0.125f;
            if (c0 + cc0 > r0 + rA + 8) v = -1e30f;
            s[2] = v; tmax1 = fmaxf(tmax1, v);

            v = (s[3] + sGb[(rA + 8) * GBW + cc0 + 1]) * 0.125f;
            if (c0 + cc0 + 1 > r0 + rA + 8) v = -1e30f;
            s[3] = v; tmax1 = fmaxf(tmax1, v);
        }

        tmax0 = fmaxf(tmax0, __shfl_xor_sync(0xffffffffu, tmax0, 1));
        tmax0 = fmaxf(tmax0, __shfl_xor_sync(0xffffffffu, tmax0, 2));
        tmax1 = fmaxf(tmax1, __shfl_xor_sync(0xffffffffu, tmax1, 1));
        tmax1 = fmaxf(tmax1, __shfl_xor_sync(0xffffffffu, tmax1, 2));

        float mn0 = fmaxf(m0r, tmax0), mn1 = fmaxf(m1r, tmax1);
        float f0s = __expf(m0r - mn0), f1s = __expf(m1r - mn1);
        float rs0 = 0.f, rs1 = 0.f;
#pragma unroll
        for (int nt = 0; nt < 8; nt++) {
            float* s = Sreg[nt];
            s[0] = __expf(s[0] - mn0); s[1] = __expf(s[1] - mn0);
            s[2] = __expf(s[2] - mn1); s[3] = __expf(s[3] - mn1);
            rs0 += s[0] + s[1];
            rs1 += s[2] + s[3];
        }
        rs0 += __shfl_xor_sync(0xffffffffu, rs0, 1);
        rs0 += __shfl_xor_sync(0xffffffffu, rs0, 2);
        rs1 += __shfl_xor_sync(0xffffffffu, rs1, 1);
        rs1 += __shfl_xor_sync(0xffffffffu, rs1, 2);

        m0r = mn0; m1r = mn1;
        l0r = l0r * f0s + rs0;
        l1r = l1r * f1s + rs1;
#pragma unroll
        for (int dn = 0; dn < 8; dn++) {
            Oacc[dn][0] *= f0s; Oacc[dn][1] *= f0s;
            Oacc[dn][2] *= f1s; Oacc[dn][3] *= f1s;
        }

        __syncwarp();
#pragma unroll
        for (int nt = 0; nt < 8; nt++) {
            int c = nt * 8 + 2 * t;
            int ch = 4 * (c >> 4) + (c & 3);
            int wd = (c & 15) >> 2;
            int s0 = swz(rA), s1 = swz(rA + 8);
            sP[(rA)     * 64 + 4 * ((ch)     ^ s0) + wd] = f2tf(Sreg[nt][0]);
            sP[(rA)     * 64 + 4 * ((ch + 1) ^ s0) + wd] = f2tf(Sreg[nt][1]);
            sP[(rA + 8) * 64 + 4 * ((ch)     ^ s1) + wd] = f2tf(Sreg[nt][2]);
            sP[(rA + 8) * 64 + 4 * ((ch + 1) ^ s1) + wd] = f2tf(Sreg[nt][3]);
        }
        __syncwarp();

        uint32_t aP[8][4];
#pragma unroll
        for (int kb = 0; kb < 4; kb++) {
            float4 f;
            f = frag4(sP, 64, rA, kb, t);
            aP[2*kb][0] = U(f.x); aP[2*kb][2] = U(f.y);
            aP[2*kb+1][0] = U(f.z); aP[2*kb+1][2] = U(f.w);
            f = frag4(sP, 64, rA + 8, kb, t);
            aP[2*kb][1] = U(f.x); aP[2*kb][3] = U(f.y);
            aP[2*kb+1][1] = U(f.z); aP[2*kb+1][3] = U(f.w);
        }

        // O += P @ V  (V^T fragments via LDS.128)
#pragma unroll
        for (int dn = 0; dn < 8; dn++) {
            const int nb = dn * 8 + g;
            float4 v0 = frag4(sVT, 64, nb, 0, t);
            float4 v1 = frag4(sVT, 64, nb, 1, t);
            float4 v2 = frag4(sVT, 64, nb, 2, t);
            float4 v3 = frag4(sVT, 64, nb, 3, t);
            mma8(Oacc[dn], aP[0][0], aP[0][1], aP[0][2], aP[0][3], U(v0.x), U(v0.y));
            mma8(Oacc[dn], aP[1][0], aP[1][1], aP[1][2], aP[1][3], U(v0.z), U(v0.w));
            mma8(Oacc[dn], aP[2][0], aP[2][1], aP[2][2], aP[2][3], U(v1.x), U(v1.y));
            mma8(Oacc[dn], aP[3][0], aP[3][1], aP[3][2], aP[3][3], U(v1.z), U(v1.w));
            mma8(Oacc[dn], aP[4][0], aP[4][1], aP[4][2], aP[4][3], U(v2.x), U(v2.y));
            mma8(Oacc[dn], aP[5][0], aP[5][1], aP[5][2], aP[5][3], U(v2.z), U(v2.w));
            mma8(Oacc[dn], aP[6][0], aP[6][1], aP[6][2], aP[6][3], U(v3.x), U(v3.y));
            mma8(Oacc[dn], aP[7][0], aP[7][1], aP[7][2], aP[7][3], U(v3.z), U(v3.w));
        }
    }

    // normalize, tf32-round (feeds gemm_out), write [b][n][h*HD+hd]
    float inv0 = 1.f / l0r, inv1 = 1.f / l1r;
    float* Og = g_O + (size_t)b * SEQ * DIM + (size_t)r0 * DIM + hcol;
#pragma unroll
    for (int dn = 0; dn < 8; dn++) {
        int d0 = dn * 8 + 2 * t;
        Og[(size_t)(rA)     * DIM + d0]     = f2tf(Oacc[dn][0] * inv0);
        Og[(size_t)(rA)     * DIM + d0 + 1] = f2tf(Oacc[dn][1] * inv0);
        Og[(size_t)(rA + 8) * DIM + d0]     = f2tf(Oacc[dn][2] * inv1);
        Og[(size_t)(rA + 8) * DIM + d0 + 1] = f2tf(Oacc[dn][3] * inv1);
    }
}

// ---------------- launch ----------------
#define QKV_SMEM_BYTES ((2*128*GP + 2*3*128*GP) * 4)

extern "C" void kernel_launch(void* const* d_in, const int* in_sizes, int n_in,
                              void* d_out, int out_size)
{
    const float* x   = (const float*)d_in[0];
    const float* Wq  = (const float*)d_in[1];
    const float* Wk  = (const float*)d_in[2];
    const float* Wv  = (const float*)d_in[3];
    const float* Wp  = (const float*)d_in[4];
    const float* bp  = (const float*)d_in[5];
    const float* rel = (const float*)d_in[6];
    float* out = (float*)d_out;

    cudaFuncSetAttribute(attn_kernel,
                         cudaFuncAttributeMaxDynamicSharedMemorySize, ATTN_SMEM_BYTES);
    cudaFuncSetAttribute(gemm_qkv,
                         cudaFuncAttributeMaxDynamicSharedMemorySize, QKV_SMEM_BYTES);

    const int nw4 = DIM * DIM / 4;      // 262144
    const int nx4 = BN * DIM / 4;       // 1048576
    cvt_tf32_k<<<(nx4 + 255) / 256, 256>>>((const float4*)x,  0, nx4);
    cvt_tf32_k<<<(nw4 + 255) / 256, 256>>>((const float4*)Wq, 1, nw4);
    cvt_tf32_k<<<(nw4 + 255) / 256, 256>>>((const float4*)Wk, 2, nw4);
    cvt_tf32_k<<<(nw4 + 255) / 256, 256>>>((const float4*)Wv, 3, nw4);
    cvt_tf32_k<<<(nw4 + 255) / 256, 256>>>((const float4*)Wp, 4, nw4);

    gemm_qkv<<<dim3(DIM / 128, BN / 128), 256, QKV_SMEM_BYTES>>>();
    attn_kernel<<<dim3(SEQ / 64, BATCH * NHEAD), 128, ATTN_SMEM_BYTES>>>(rel);
    gemm_out<<<dim3(DIM / 128, BN / 128), 256>>>(bp, out);
}